// round 15
// baseline (speedup 1.0000x reference)
#include <cuda_runtime.h>
#include <cuda_fp16.h>
#include <cuda_pipeline_primitives.h>

#define HH 2048
#define WW 2048
#define W4 (WW/4)
#define HWN (HH*WW)
#define HWN4 (HWN/4)
#define RAD 10
#define THR 1e-3f
#define EPSF 1e-9f

// Padded fp16 scratch planes: 12 zeros left, 20 zeros right (never written).
#define WPH (WW + 12 + 20)      // 2080 halves per row

__device__ __half g_P0[HH * WPH];  // vertical box of mask (padded fp16: exact ints)
__device__ __half g_P1[HH * WPH];  // vertical box of b, later of S1 (padded fp16)
__device__ __half g_P2[HH * WPH];  // vertical box of b*b, later of S2 (padded fp16)
__device__ __half g_S1[HWN];       // elementwise S1 (dense fp16)
__device__ __half g_S2[HWN];       // elementwise S2 (dense fp16)
__device__ double g_acc[8];
__device__ double g_loss;
__device__ unsigned g_tickA;
__device__ unsigned g_tickB;
__device__ float g_v[4];

// ---- helpers ----------------------------------------------------------------
__device__ __forceinline__ float4 f4z() { return make_float4(0.f, 0.f, 0.f, 0.f); }
__device__ __forceinline__ float4 f4add(float4 a, float4 b) {
    return make_float4(a.x + b.x, a.y + b.y, a.z + b.z, a.w + b.w);
}
__device__ __forceinline__ float4 f4sub(float4 a, float4 b) {
    return make_float4(a.x - b.x, a.y - b.y, a.z - b.z, a.w - b.w);
}
__device__ __forceinline__ float4 f4mul(float4 a, float4 b) {
    return make_float4(a.x * b.x, a.y * b.y, a.z * b.z, a.w * b.w);
}
__device__ __forceinline__ float4 f4mask(float4 i) {
    return make_float4(i.x > THR ? 1.f : 0.f, i.y > THR ? 1.f : 0.f,
                       i.z > THR ? 1.f : 0.f, i.w > THR ? 1.f : 0.f);
}
__device__ __forceinline__ uint2 f4_to_h4(float4 s) {
    __half2 lo = __floats2half2_rn(s.x, s.y);
    __half2 hi = __floats2half2_rn(s.z, s.w);
    uint2 r;
    r.x = *(unsigned*)&lo;
    r.y = *(unsigned*)&hi;
    return r;
}
__device__ __forceinline__ float4 h4_to_f4(uint2 v) {
    __half2 lo = *(__half2*)&v.x;
    __half2 hi = *(__half2*)&v.y;
    float2 a = __half22float2(lo), b = __half22float2(hi);
    return make_float4(a.x, a.y, b.x, b.y);
}

// ---------------------------------------------------------------------------
// K1: vertical 21-tap box of {mask(I), b, b*b} -> padded fp16 planes.
// cp.async smem staging, two passes (I then b) reusing one 36.8KB buffer.
// Per-thread private column -> NO barriers. grid (W4/64, HH/SEG1), block 64.
// ---------------------------------------------------------------------------
#define K1_T 64
#define SEG1 16
#define NROW1 (SEG1 + 2 * RAD)   // 36 rows; smem = 36*64*16 = 36,864 B

__global__ void __launch_bounds__(K1_T) k1_vert(const float4* __restrict__ I4,
                                                const float4* __restrict__ B4) {
    __shared__ __align__(16) float4 sb[NROW1][K1_T];
    int tx = threadIdx.x;
    int col = blockIdx.x * K1_T + tx;
    int r0 = blockIdx.y * SEG1;

    // ---- pass A: I -> mask plane P0 ----
#pragma unroll
    for (int j = 0; j < NROW1; ++j) {
        int y = r0 - RAD + j;
        if ((unsigned)y < (unsigned)HH)
            __pipeline_memcpy_async(&sb[j][tx], I4 + y * W4 + col, 16);
        else
            sb[j][tx] = f4z();
    }
    __pipeline_commit();
    __pipeline_wait_prior(0);

    {
        float4 s0 = f4z();
#pragma unroll
        for (int j = 0; j < 21; ++j) s0 = f4add(s0, f4mask(sb[j][tx]));
#pragma unroll
        for (int i = 0; i < SEG1; ++i) {
            int oh = (r0 + i) * WPH + 12 + 4 * col;
            *(uint2*)(g_P0 + oh) = f4_to_h4(s0);
            if (i < SEG1 - 1)
                s0 = f4add(s0, f4sub(f4mask(sb[21 + i][tx]), f4mask(sb[i][tx])));
        }
    }

    // ---- pass B: b -> P1 (sum b), P2 (sum b^2) ----
#pragma unroll
    for (int j = 0; j < NROW1; ++j) {
        int y = r0 - RAD + j;
        if ((unsigned)y < (unsigned)HH)
            __pipeline_memcpy_async(&sb[j][tx], B4 + y * W4 + col, 16);
        else
            sb[j][tx] = f4z();
    }
    __pipeline_commit();
    __pipeline_wait_prior(0);

    {
        float4 s1 = f4z(), s2 = f4z();
#pragma unroll
        for (int j = 0; j < 21; ++j) {
            float4 bv = sb[j][tx];
            s1 = f4add(s1, bv);
            s2 = f4add(s2, f4mul(bv, bv));
        }
#pragma unroll
        for (int i = 0; i < SEG1; ++i) {
            int oh = (r0 + i) * WPH + 12 + 4 * col;
            *(uint2*)(g_P1 + oh) = f4_to_h4(s1);
            *(uint2*)(g_P2 + oh) = f4_to_h4(s2);
            if (i < SEG1 - 1) {
                float4 ba = sb[21 + i][tx], br = sb[i][tx];
                s1 = f4add(s1, f4sub(ba, br));
                s2 = f4add(s2, f4sub(f4mul(ba, ba), f4mul(br, br)));
            }
        }
    }
}

// ---------------------------------------------------------------------------
// Register sliding-window horizontal 21-tap box over fp16 padded plane.
// Produces 8 pixels starting at pixel 8*xo; loads 4 uint4 (32 halves).
// ---------------------------------------------------------------------------
__device__ __forceinline__ void hbox8h(const __half* __restrict__ plane,
                                       int rbh, int xo, float* out) {
    const uint4* p4 = (const uint4*)(plane + rbh);
    float f[32];
#pragma unroll
    for (int j = 0; j < 4; ++j) {
        uint4 v = __ldg(p4 + xo + j);
        __half2 h0 = *(__half2*)&v.x, h1 = *(__half2*)&v.y;
        __half2 h2 = *(__half2*)&v.z, h3 = *(__half2*)&v.w;
        float2 a = __half22float2(h0), b = __half22float2(h1);
        float2 c = __half22float2(h2), d = __half22float2(h3);
        int o = 8 * j;
        f[o] = a.x; f[o + 1] = a.y; f[o + 2] = b.x; f[o + 3] = b.y;
        f[o + 4] = c.x; f[o + 5] = c.y; f[o + 6] = d.x; f[o + 7] = d.y;
    }
    float s = 0.f;
#pragma unroll
    for (int k = 2; k <= 22; ++k) s += f[k];
    out[0] = s;
#pragma unroll
    for (int i = 1; i < 8; ++i) { s += f[22 + i] - f[1 + i]; out[i] = s; }
}

// ---------------------------------------------------------------------------
// K2: horizontal box of 3 fp16 planes + 8-channel reduction via fp64 atomics.
// grid (2, HH), block 128 — each block does a 1024-px half row.
// ---------------------------------------------------------------------------
__global__ void __launch_bounds__(128) k2_hor(const float4* __restrict__ I4,
                                              const float4* __restrict__ e4,
                                              const float4* __restrict__ u4) {
    __shared__ float sred[32];
    int t = threadIdx.x;
    int row = blockIdx.y;
    int xo = blockIdx.x * 128 + t;     // uint4 index within padded row / 8-px group
    int rbh = row * WPH;
    int o = row * W4 + 2 * xo;

    // hoisted independent global loads
    float4 Iv0 = __ldg(I4 + o),     Iv1 = __ldg(I4 + o + 1);
    float4 ev0 = __ldg(e4 + o),     ev1 = __ldg(e4 + o + 1);
    float4 A0  = __ldg(u4 + o),                 A1 = __ldg(u4 + o + 1);
    float4 B0  = __ldg(u4 + HWN4 + o),          B1 = __ldg(u4 + HWN4 + o + 1);
    float4 C0  = __ldg(u4 + 2 * HWN4 + o),      C1 = __ldg(u4 + 2 * HWN4 + o + 1);
    float4 D0  = __ldg(u4 + 3 * HWN4 + o),      D1 = __ldg(u4 + 3 * HWN4 + o + 1);

    float norm[8], bK[8], b2K[8];
    hbox8h(g_P0, rbh, xo, norm);
    hbox8h(g_P1, rbh, xo, bK);
    hbox8h(g_P2, rbh, xo, b2K);

    float a[8] = {0, 0, 0, 0, 0, 0, 0, 0};
    const float4 Ivs[2] = {Iv0, Iv1}, evs[2] = {ev0, ev1};
    const float4 Us0[2] = {A0, A1}, Us1[2] = {B0, B1};
    const float4 Us2[2] = {C0, C1}, Us3[2] = {D0, D1};
#pragma unroll
    for (int h = 0; h < 2; ++h) {
        const float* fI = (const float*)&Ivs[h];
        const float* fe = (const float*)&evs[h];
        const float* f0 = (const float*)&Us0[h];
        const float* f1 = (const float*)&Us1[h];
        const float* f2 = (const float*)&Us2[h];
        const float* f3 = (const float*)&Us3[h];
#pragma unroll
        for (int c = 0; c < 4; ++c) {
            int i = 4 * h + c;
            float inv = 1.f / (norm[i] + EPSF);
            float bKc = bK[i] * inv;
            float b2Kc = b2K[i] * inv;
            float p0 = f0[c] * f0[c], p1 = f1[c] * f1[c];
            float p2 = f2[c] * f2[c], p3 = f3[c] * f3[c];
            float A = (fI[c] - fe[c]) * bKc;
            a[0] += fI[c] * p0; a[1] += p0;
            a[2] += A * p1;  a[3] += A * p2;  a[4] += A * p3;
            a[5] += b2Kc * p1; a[6] += b2Kc * p2; a[7] += b2Kc * p3;
        }
    }
    int lane = t & 31, w = t >> 5;
#pragma unroll
    for (int c = 0; c < 8; ++c) {
        float v = a[c];
#pragma unroll
        for (int off = 16; off; off >>= 1) v += __shfl_down_sync(0xffffffffu, v, off);
        if (lane == 0) sred[w * 8 + c] = v;
    }
    __syncthreads();
    if (t < 8) {
        double s = 0;
#pragma unroll
        for (int ww2 = 0; ww2 < 4; ++ww2) s += (double)sred[ww2 * 8 + t];
        atomicAdd(&g_acc[t], s);
    }
    __syncthreads();
    if (t == 0) {
        __threadfence();
        unsigned tk = atomicAdd(&g_tickA, 1u);
        if (tk == (unsigned)(2 * HH - 1)) {
            double tot[8];
#pragma unroll
            for (int c = 0; c < 8; ++c) tot[c] = atomicAdd(&g_acc[c], 0.0);
            g_v[0] = (float)(tot[0] / (tot[1] + 1e-9));
            g_v[1] = (float)(tot[2] / (tot[5] + 1e-9));
            g_v[2] = (float)(tot[3] / (tot[6] + 1e-9));
            g_v[3] = (float)(tot[4] / (tot[7] + 1e-9));
#pragma unroll
            for (int c = 0; c < 8; ++c) g_acc[c] = 0.0;
            g_tickA = 0u;
        }
    }
}

// ---------------------------------------------------------------------------
// K4a: elementwise S1=(I-e)*sum(v*up), S2=sum(v^2*up) -> dense fp16 planes.
// ---------------------------------------------------------------------------
__global__ void k4a_elem(const float4* __restrict__ I4, const float4* __restrict__ e4,
                         const float4* __restrict__ u4) {
    int idx = blockIdx.x * 256 + threadIdx.x;
    float v0 = g_v[0], v1 = g_v[1], v2 = g_v[2], v3 = g_v[3];
    float w0 = v0 * v0, w1 = v1 * v1, w2 = v2 * v2, w3 = v3 * v3;
    float4 Iv = __ldg(I4 + idx), ev = __ldg(e4 + idx);
    float4 U0 = __ldg(u4 + idx), U1 = __ldg(u4 + HWN4 + idx);
    float4 U2 = __ldg(u4 + 2 * HWN4 + idx), U3 = __ldg(u4 + 3 * HWN4 + idx);
    float4 P0 = f4mul(U0, U0), P1 = f4mul(U1, U1);
    float4 P2 = f4mul(U2, U2), P3 = f4mul(U3, U3);
    float4 s1, s2;
    s1.x = (Iv.x - ev.x) * (v0 * P0.x + v1 * P1.x + v2 * P2.x + v3 * P3.x);
    s1.y = (Iv.y - ev.y) * (v0 * P0.y + v1 * P1.y + v2 * P2.y + v3 * P3.y);
    s1.z = (Iv.z - ev.z) * (v0 * P0.z + v1 * P1.z + v2 * P2.z + v3 * P3.z);
    s1.w = (Iv.w - ev.w) * (v0 * P0.w + v1 * P1.w + v2 * P2.w + v3 * P3.w);
    s2.x = w0 * P0.x + w1 * P1.x + w2 * P2.x + w3 * P3.x;
    s2.y = w0 * P0.y + w1 * P1.y + w2 * P2.y + w3 * P3.y;
    s2.z = w0 * P0.z + w1 * P1.z + w2 * P2.z + w3 * P3.z;
    s2.w = w0 * P0.w + w1 * P1.w + w2 * P2.w + w3 * P3.w;
    *(uint2*)(g_S1 + 4 * idx) = f4_to_h4(s1);
    *(uint2*)(g_S2 + 4 * idx) = f4_to_h4(s2);
}

// ---------------------------------------------------------------------------
// K4b: vertical box of fp16 S1,S2 -> fp16 P1,P2 (padded out).
// SEGB=16, two single-plane passes sharing one 36.8KB smem buffer.
// Block 128 (vs 64): higher occupancy. NO barriers (per-thread columns).
// grid (W4/128, HH/SEGB) = (4, 128), block 128.
// ---------------------------------------------------------------------------
#define K4B_T 128
#define SEGB 16
#define NROWB (SEGB + 2 * RAD)   // 36 rows; smem = 36*128*8 = 36,864 B

__device__ __forceinline__ void k4b_pass(const uint2* __restrict__ S,
                                         __half* __restrict__ P,
                                         uint2 (*sb)[K4B_T],
                                         int tx, int col, int r0) {
#pragma unroll
    for (int j = 0; j < NROWB; ++j) {
        int y = r0 - RAD + j;
        if ((unsigned)y < (unsigned)HH) {
            __pipeline_memcpy_async(&sb[j][tx], S + y * W4 + col, 8);
        } else {
            sb[j][tx] = make_uint2(0u, 0u);
        }
    }
    __pipeline_commit();
    __pipeline_wait_prior(0);

    float4 s = f4z();
#pragma unroll
    for (int j = 0; j < 21; ++j) s = f4add(s, h4_to_f4(sb[j][tx]));
#pragma unroll
    for (int i = 0; i < SEGB; ++i) {
        int oh = (r0 + i) * WPH + 12 + 4 * col;
        *(uint2*)(P + oh) = f4_to_h4(s);
        if (i < SEGB - 1)
            s = f4add(s, f4sub(h4_to_f4(sb[21 + i][tx]), h4_to_f4(sb[i][tx])));
    }
}

__global__ void __launch_bounds__(K4B_T) k4b_vert() {
    __shared__ __align__(16) uint2 sb[NROWB][K4B_T];
    int tx = threadIdx.x;
    int col = blockIdx.x * K4B_T + tx;
    int r0 = blockIdx.y * SEGB;
    k4b_pass((const uint2*)g_S1, g_P1, sb, tx, col, r0);
    k4b_pass((const uint2*)g_S2, g_P2, sb, tx, col, r0);
}

// ---------------------------------------------------------------------------
// K5: horizontal box of fp16 {norm, S1v, S2v}; masked combine; loss ->d_out.
// grid (2, HH), block 128.
// ---------------------------------------------------------------------------
__global__ void __launch_bounds__(128) k5_hor(const float4* __restrict__ I4,
                                              const float4* __restrict__ B4,
                                              float* __restrict__ out) {
    __shared__ double sw[4];
    int t = threadIdx.x;
    int row = blockIdx.y;
    int xo = blockIdx.x * 128 + t;
    int rbh = row * WPH;
    int o = row * W4 + 2 * xo;

    float4 Iv0 = __ldg(I4 + o), Iv1 = __ldg(I4 + o + 1);
    float4 Bv0 = __ldg(B4 + o), Bv1 = __ldg(B4 + o + 1);

    float norm[8], bd[8], db[8];
    hbox8h(g_P0, rbh, xo, norm);
    hbox8h(g_P1, rbh, xo, bd);
    hbox8h(g_P2, rbh, xo, db);

    float acc = 0.f;
    const float4 Ivs[2] = {Iv0, Iv1}, Bvs[2] = {Bv0, Bv1};
#pragma unroll
    for (int h = 0; h < 2; ++h) {
        const float* fI = (const float*)&Ivs[h];
        const float* fB = (const float*)&Bvs[h];
#pragma unroll
        for (int c = 0; c < 4; ++c) {
            int i = 4 * h + c;
            float inv = 1.f / (norm[i] + EPSF);
            float bdc = bd[i] * inv;
            float dbc = db[i] * inv;
            float m = (fI[c] > THR) ? 1.f : 0.f;
            bdc = bdc * m + (1.f - m);
            dbc = dbc * m + (1.f - m);
            float bn = bdc / (dbc + EPSF);
            float d = fB[c] - bn;
            acc += d * d;
        }
    }
    int lane = t & 31, w = t >> 5;
#pragma unroll
    for (int off = 16; off; off >>= 1) acc += __shfl_down_sync(0xffffffffu, acc, off);
    if (lane == 0) sw[w] = (double)acc;
    __syncthreads();
    if (t == 0) {
        double s = sw[0] + sw[1] + sw[2] + sw[3];
        atomicAdd(&g_loss, s);
        __threadfence();
        unsigned tk = atomicAdd(&g_tickB, 1u);
        if (tk == (unsigned)(2 * HH - 1)) {
            double tot = atomicAdd(&g_loss, 0.0);
            out[0] = (float)(tot / (double)HWN);
            g_loss = 0.0;
            g_tickB = 0u;
        }
    }
}

// ---------------------------------------------------------------------------
extern "C" void kernel_launch(void* const* d_in, const int* in_sizes, int n_in,
                              void* d_out, int out_size) {
    (void)in_sizes; (void)n_in; (void)out_size;
    const float4* I = (const float4*)d_in[0];
    const float4* u = (const float4*)d_in[1];
    const float4* b = (const float4*)d_in[2];
    const float4* e = (const float4*)d_in[3];

    dim3 g1(W4 / K1_T, HH / SEG1);   // (8, 128) for k1
    dim3 g4(W4 / K4B_T, HH / SEGB);  // (4, 128) for k4b
    dim3 gh(2, HH);                  // half-row blocks for k2/k5

    k1_vert<<<g1, K1_T>>>(I, b);
    k2_hor<<<gh, 128>>>(I, e, u);
    k4a_elem<<<HWN4 / 256, 256>>>(I, e, u);
    k4b_vert<<<g4, K4B_T>>>();
    k5_hor<<<gh, 128>>>(I, b, (float*)d_out);
}

// round 16
// speedup vs baseline: 1.0257x; 1.0257x over previous
#include <cuda_runtime.h>
#include <cuda_fp16.h>
#include <cuda_pipeline_primitives.h>

#define HH 2048
#define WW 2048
#define W4 (WW/4)
#define HWN (HH*WW)
#define HWN4 (HWN/4)
#define RAD 10
#define THR 1e-3f
#define EPSF 1e-9f

// Padded fp16 scratch planes: 12 zeros left, 20 zeros right (never written).
#define WPH (WW + 12 + 20)      // 2080 halves per row

__device__ __half g_P0[HH * WPH];  // vertical box of mask (padded fp16: exact ints)
__device__ __half g_P1[HH * WPH];  // vertical box of b, later of S1 (padded fp16)
__device__ __half g_P2[HH * WPH];  // vertical box of b*b, later of S2 (padded fp16)
__device__ __half g_S1[HWN];       // elementwise S1 (dense fp16)
__device__ __half g_S2[HWN];       // elementwise S2 (dense fp16)
__device__ double g_acc[8];
__device__ double g_loss;
__device__ unsigned g_tickA;
__device__ unsigned g_tickB;
__device__ float g_v[4];

// ---- helpers ----------------------------------------------------------------
__device__ __forceinline__ float4 f4z() { return make_float4(0.f, 0.f, 0.f, 0.f); }
__device__ __forceinline__ float4 f4add(float4 a, float4 b) {
    return make_float4(a.x + b.x, a.y + b.y, a.z + b.z, a.w + b.w);
}
__device__ __forceinline__ float4 f4sub(float4 a, float4 b) {
    return make_float4(a.x - b.x, a.y - b.y, a.z - b.z, a.w - b.w);
}
__device__ __forceinline__ float4 f4mul(float4 a, float4 b) {
    return make_float4(a.x * b.x, a.y * b.y, a.z * b.z, a.w * b.w);
}
__device__ __forceinline__ float4 f4mask(float4 i) {
    return make_float4(i.x > THR ? 1.f : 0.f, i.y > THR ? 1.f : 0.f,
                       i.z > THR ? 1.f : 0.f, i.w > THR ? 1.f : 0.f);
}
__device__ __forceinline__ uint2 f4_to_h4(float4 s) {
    __half2 lo = __floats2half2_rn(s.x, s.y);
    __half2 hi = __floats2half2_rn(s.z, s.w);
    uint2 r;
    r.x = *(unsigned*)&lo;
    r.y = *(unsigned*)&hi;
    return r;
}
__device__ __forceinline__ float4 h4_to_f4(uint2 v) {
    __half2 lo = *(__half2*)&v.x;
    __half2 hi = *(__half2*)&v.y;
    float2 a = __half22float2(lo), b = __half22float2(hi);
    return make_float4(a.x, a.y, b.x, b.y);
}

// ---------------------------------------------------------------------------
// K1: vertical 21-tap box of {mask(I), b, b*b} -> padded fp16 planes.
// SEG1=32 (amp 1.625), cp.async into 53.2KB dynamic smem, two serial passes.
// Per-thread private column -> NO barriers. grid (W4/64, HH/SEG1), block 64.
// ---------------------------------------------------------------------------
#define K1_T 64
#define SEG1 32
#define NROW1 (SEG1 + 2 * RAD)   // 52 rows; smem = 52*64*16 = 53,248 B
#define K1_SMEM (NROW1 * K1_T * 16)

extern __shared__ __align__(16) unsigned char dynsmem[];

__global__ void __launch_bounds__(K1_T) k1_vert(const float4* __restrict__ I4,
                                                const float4* __restrict__ B4) {
    float4* sb = (float4*)dynsmem;   // [NROW1][K1_T]
    int tx = threadIdx.x;
    int col = blockIdx.x * K1_T + tx;
    int r0 = blockIdx.y * SEG1;

    // ---- pass A: I -> mask plane P0 ----
    for (int j = 0; j < NROW1; ++j) {
        int y = r0 - RAD + j;
        if ((unsigned)y < (unsigned)HH)
            __pipeline_memcpy_async(&sb[j * K1_T + tx], I4 + y * W4 + col, 16);
        else
            sb[j * K1_T + tx] = f4z();
    }
    __pipeline_commit();
    __pipeline_wait_prior(0);

    {
        float4 s0 = f4z();
#pragma unroll
        for (int j = 0; j < 21; ++j) s0 = f4add(s0, f4mask(sb[j * K1_T + tx]));
#pragma unroll 8
        for (int i = 0; i < SEG1; ++i) {
            int oh = (r0 + i) * WPH + 12 + 4 * col;
            *(uint2*)(g_P0 + oh) = f4_to_h4(s0);
            if (i < SEG1 - 1)
                s0 = f4add(s0, f4sub(f4mask(sb[(21 + i) * K1_T + tx]),
                                     f4mask(sb[i * K1_T + tx])));
        }
    }

    // ---- pass B: b -> P1 (sum b), P2 (sum b^2) ----
    for (int j = 0; j < NROW1; ++j) {
        int y = r0 - RAD + j;
        if ((unsigned)y < (unsigned)HH)
            __pipeline_memcpy_async(&sb[j * K1_T + tx], B4 + y * W4 + col, 16);
        else
            sb[j * K1_T + tx] = f4z();
    }
    __pipeline_commit();
    __pipeline_wait_prior(0);

    {
        float4 s1 = f4z(), s2 = f4z();
#pragma unroll
        for (int j = 0; j < 21; ++j) {
            float4 bv = sb[j * K1_T + tx];
            s1 = f4add(s1, bv);
            s2 = f4add(s2, f4mul(bv, bv));
        }
#pragma unroll 8
        for (int i = 0; i < SEG1; ++i) {
            int oh = (r0 + i) * WPH + 12 + 4 * col;
            *(uint2*)(g_P1 + oh) = f4_to_h4(s1);
            *(uint2*)(g_P2 + oh) = f4_to_h4(s2);
            if (i < SEG1 - 1) {
                float4 ba = sb[(21 + i) * K1_T + tx], br = sb[i * K1_T + tx];
                s1 = f4add(s1, f4sub(ba, br));
                s2 = f4add(s2, f4sub(f4mul(ba, ba), f4mul(br, br)));
            }
        }
    }
}

// ---------------------------------------------------------------------------
// Register sliding-window horizontal 21-tap box over fp16 padded plane.
// Produces 8 pixels starting at pixel 8*xo; loads 4 uint4 (32 halves).
// ---------------------------------------------------------------------------
__device__ __forceinline__ void hbox8h(const __half* __restrict__ plane,
                                       int rbh, int xo, float* out) {
    const uint4* p4 = (const uint4*)(plane + rbh);
    float f[32];
#pragma unroll
    for (int j = 0; j < 4; ++j) {
        uint4 v = __ldg(p4 + xo + j);
        __half2 h0 = *(__half2*)&v.x, h1 = *(__half2*)&v.y;
        __half2 h2 = *(__half2*)&v.z, h3 = *(__half2*)&v.w;
        float2 a = __half22float2(h0), b = __half22float2(h1);
        float2 c = __half22float2(h2), d = __half22float2(h3);
        int o = 8 * j;
        f[o] = a.x; f[o + 1] = a.y; f[o + 2] = b.x; f[o + 3] = b.y;
        f[o + 4] = c.x; f[o + 5] = c.y; f[o + 6] = d.x; f[o + 7] = d.y;
    }
    float s = 0.f;
#pragma unroll
    for (int k = 2; k <= 22; ++k) s += f[k];
    out[0] = s;
#pragma unroll
    for (int i = 1; i < 8; ++i) { s += f[22 + i] - f[1 + i]; out[i] = s; }
}

// ---------------------------------------------------------------------------
// K2: horizontal box of 3 fp16 planes + 8-channel reduction via fp64 atomics.
// grid (2, HH), block 128 — each block does a 1024-px half row.
// ---------------------------------------------------------------------------
__global__ void __launch_bounds__(128) k2_hor(const float4* __restrict__ I4,
                                              const float4* __restrict__ e4,
                                              const float4* __restrict__ u4) {
    __shared__ float sred[32];
    int t = threadIdx.x;
    int row = blockIdx.y;
    int xo = blockIdx.x * 128 + t;     // uint4 index within padded row / 8-px group
    int rbh = row * WPH;
    int o = row * W4 + 2 * xo;

    // hoisted independent global loads
    float4 Iv0 = __ldg(I4 + o),     Iv1 = __ldg(I4 + o + 1);
    float4 ev0 = __ldg(e4 + o),     ev1 = __ldg(e4 + o + 1);
    float4 A0  = __ldg(u4 + o),                 A1 = __ldg(u4 + o + 1);
    float4 B0  = __ldg(u4 + HWN4 + o),          B1 = __ldg(u4 + HWN4 + o + 1);
    float4 C0  = __ldg(u4 + 2 * HWN4 + o),      C1 = __ldg(u4 + 2 * HWN4 + o + 1);
    float4 D0  = __ldg(u4 + 3 * HWN4 + o),      D1 = __ldg(u4 + 3 * HWN4 + o + 1);

    float norm[8], bK[8], b2K[8];
    hbox8h(g_P0, rbh, xo, norm);
    hbox8h(g_P1, rbh, xo, bK);
    hbox8h(g_P2, rbh, xo, b2K);

    float a[8] = {0, 0, 0, 0, 0, 0, 0, 0};
    const float4 Ivs[2] = {Iv0, Iv1}, evs[2] = {ev0, ev1};
    const float4 Us0[2] = {A0, A1}, Us1[2] = {B0, B1};
    const float4 Us2[2] = {C0, C1}, Us3[2] = {D0, D1};
#pragma unroll
    for (int h = 0; h < 2; ++h) {
        const float* fI = (const float*)&Ivs[h];
        const float* fe = (const float*)&evs[h];
        const float* f0 = (const float*)&Us0[h];
        const float* f1 = (const float*)&Us1[h];
        const float* f2 = (const float*)&Us2[h];
        const float* f3 = (const float*)&Us3[h];
#pragma unroll
        for (int c = 0; c < 4; ++c) {
            int i = 4 * h + c;
            float inv = 1.f / (norm[i] + EPSF);
            float bKc = bK[i] * inv;
            float b2Kc = b2K[i] * inv;
            float p0 = f0[c] * f0[c], p1 = f1[c] * f1[c];
            float p2 = f2[c] * f2[c], p3 = f3[c] * f3[c];
            float A = (fI[c] - fe[c]) * bKc;
            a[0] += fI[c] * p0; a[1] += p0;
            a[2] += A * p1;  a[3] += A * p2;  a[4] += A * p3;
            a[5] += b2Kc * p1; a[6] += b2Kc * p2; a[7] += b2Kc * p3;
        }
    }
    int lane = t & 31, w = t >> 5;
#pragma unroll
    for (int c = 0; c < 8; ++c) {
        float v = a[c];
#pragma unroll
        for (int off = 16; off; off >>= 1) v += __shfl_down_sync(0xffffffffu, v, off);
        if (lane == 0) sred[w * 8 + c] = v;
    }
    __syncthreads();
    if (t < 8) {
        double s = 0;
#pragma unroll
        for (int ww2 = 0; ww2 < 4; ++ww2) s += (double)sred[ww2 * 8 + t];
        atomicAdd(&g_acc[t], s);
    }
    __syncthreads();
    if (t == 0) {
        __threadfence();
        unsigned tk = atomicAdd(&g_tickA, 1u);
        if (tk == (unsigned)(2 * HH - 1)) {
            double tot[8];
#pragma unroll
            for (int c = 0; c < 8; ++c) tot[c] = atomicAdd(&g_acc[c], 0.0);
            g_v[0] = (float)(tot[0] / (tot[1] + 1e-9));
            g_v[1] = (float)(tot[2] / (tot[5] + 1e-9));
            g_v[2] = (float)(tot[3] / (tot[6] + 1e-9));
            g_v[3] = (float)(tot[4] / (tot[7] + 1e-9));
#pragma unroll
            for (int c = 0; c < 8; ++c) g_acc[c] = 0.0;
            g_tickA = 0u;
        }
    }
}

// ---------------------------------------------------------------------------
// K4a: elementwise S1=(I-e)*sum(v*up), S2=sum(v^2*up) -> dense fp16 planes.
// ---------------------------------------------------------------------------
__global__ void k4a_elem(const float4* __restrict__ I4, const float4* __restrict__ e4,
                         const float4* __restrict__ u4) {
    int idx = blockIdx.x * 256 + threadIdx.x;
    float v0 = g_v[0], v1 = g_v[1], v2 = g_v[2], v3 = g_v[3];
    float w0 = v0 * v0, w1 = v1 * v1, w2 = v2 * v2, w3 = v3 * v3;
    float4 Iv = __ldg(I4 + idx), ev = __ldg(e4 + idx);
    float4 U0 = __ldg(u4 + idx), U1 = __ldg(u4 + HWN4 + idx);
    float4 U2 = __ldg(u4 + 2 * HWN4 + idx), U3 = __ldg(u4 + 3 * HWN4 + idx);
    float4 P0 = f4mul(U0, U0), P1 = f4mul(U1, U1);
    float4 P2 = f4mul(U2, U2), P3 = f4mul(U3, U3);
    float4 s1, s2;
    s1.x = (Iv.x - ev.x) * (v0 * P0.x + v1 * P1.x + v2 * P2.x + v3 * P3.x);
    s1.y = (Iv.y - ev.y) * (v0 * P0.y + v1 * P1.y + v2 * P2.y + v3 * P3.y);
    s1.z = (Iv.z - ev.z) * (v0 * P0.z + v1 * P1.z + v2 * P2.z + v3 * P3.z);
    s1.w = (Iv.w - ev.w) * (v0 * P0.w + v1 * P1.w + v2 * P2.w + v3 * P3.w);
    s2.x = w0 * P0.x + w1 * P1.x + w2 * P2.x + w3 * P3.x;
    s2.y = w0 * P0.y + w1 * P1.y + w2 * P2.y + w3 * P3.y;
    s2.z = w0 * P0.z + w1 * P1.z + w2 * P2.z + w3 * P3.z;
    s2.w = w0 * P0.w + w1 * P1.w + w2 * P2.w + w3 * P3.w;
    *(uint2*)(g_S1 + 4 * idx) = f4_to_h4(s1);
    *(uint2*)(g_S2 + 4 * idx) = f4_to_h4(s2);
}

// ---------------------------------------------------------------------------
// K4b: vertical box of fp16 S1,S2 -> fp16 P1,P2 (padded out).
// SEGB=32 (amp 1.625), block 64, TWO pipelined buffers: S2's fill overlaps
// S1's compute. NO barriers (per-thread columns). grid (W4/64, HH/SEGB).
// ---------------------------------------------------------------------------
#define K4B_T 64
#define SEGB 32
#define NROWB (SEGB + 2 * RAD)   // 52 rows; smem = 2 * 52*64*8 = 53,248 B
#define K4B_SMEM (2 * NROWB * K4B_T * 8)

__device__ __forceinline__ void k4b_fill(const uint2* __restrict__ S,
                                         uint2* __restrict__ sb,
                                         int tx, int col, int r0) {
    for (int j = 0; j < NROWB; ++j) {
        int y = r0 - RAD + j;
        if ((unsigned)y < (unsigned)HH)
            __pipeline_memcpy_async(&sb[j * K4B_T + tx], S + y * W4 + col, 8);
        else
            sb[j * K4B_T + tx] = make_uint2(0u, 0u);
    }
    __pipeline_commit();
}

__device__ __forceinline__ void k4b_compute(const uint2* __restrict__ sb,
                                            __half* __restrict__ P,
                                            int tx, int col, int r0) {
    float4 s = f4z();
#pragma unroll
    for (int j = 0; j < 21; ++j) s = f4add(s, h4_to_f4(sb[j * K4B_T + tx]));
#pragma unroll 8
    for (int i = 0; i < SEGB; ++i) {
        int oh = (r0 + i) * WPH + 12 + 4 * col;
        *(uint2*)(P + oh) = f4_to_h4(s);
        if (i < SEGB - 1)
            s = f4add(s, f4sub(h4_to_f4(sb[(21 + i) * K4B_T + tx]),
                               h4_to_f4(sb[i * K4B_T + tx])));
    }
}

__global__ void __launch_bounds__(K4B_T) k4b_vert() {
    uint2* sb1 = (uint2*)dynsmem;
    uint2* sb2 = sb1 + NROWB * K4B_T;
    int tx = threadIdx.x;
    int col = blockIdx.x * K4B_T + tx;
    int r0 = blockIdx.y * SEGB;

    k4b_fill((const uint2*)g_S1, sb1, tx, col, r0);   // group 0
    k4b_fill((const uint2*)g_S2, sb2, tx, col, r0);   // group 1
    __pipeline_wait_prior(1);                          // S1 ready
    k4b_compute(sb1, g_P1, tx, col, r0);
    __pipeline_wait_prior(0);                          // S2 ready
    k4b_compute(sb2, g_P2, tx, col, r0);
}

// ---------------------------------------------------------------------------
// K5: horizontal box of fp16 {norm, S1v, S2v}; masked combine; loss ->d_out.
// grid (2, HH), block 128.
// ---------------------------------------------------------------------------
__global__ void __launch_bounds__(128) k5_hor(const float4* __restrict__ I4,
                                              const float4* __restrict__ B4,
                                              float* __restrict__ out) {
    __shared__ double sw[4];
    int t = threadIdx.x;
    int row = blockIdx.y;
    int xo = blockIdx.x * 128 + t;
    int rbh = row * WPH;
    int o = row * W4 + 2 * xo;

    float4 Iv0 = __ldg(I4 + o), Iv1 = __ldg(I4 + o + 1);
    float4 Bv0 = __ldg(B4 + o), Bv1 = __ldg(B4 + o + 1);

    float norm[8], bd[8], db[8];
    hbox8h(g_P0, rbh, xo, norm);
    hbox8h(g_P1, rbh, xo, bd);
    hbox8h(g_P2, rbh, xo, db);

    float acc = 0.f;
    const float4 Ivs[2] = {Iv0, Iv1}, Bvs[2] = {Bv0, Bv1};
#pragma unroll
    for (int h = 0; h < 2; ++h) {
        const float* fI = (const float*)&Ivs[h];
        const float* fB = (const float*)&Bvs[h];
#pragma unroll
        for (int c = 0; c < 4; ++c) {
            int i = 4 * h + c;
            float inv = 1.f / (norm[i] + EPSF);
            float bdc = bd[i] * inv;
            float dbc = db[i] * inv;
            float m = (fI[c] > THR) ? 1.f : 0.f;
            bdc = bdc * m + (1.f - m);
            dbc = dbc * m + (1.f - m);
            float bn = bdc / (dbc + EPSF);
            float d = fB[c] - bn;
            acc += d * d;
        }
    }
    int lane = t & 31, w = t >> 5;
#pragma unroll
    for (int off = 16; off; off >>= 1) acc += __shfl_down_sync(0xffffffffu, acc, off);
    if (lane == 0) sw[w] = (double)acc;
    __syncthreads();
    if (t == 0) {
        double s = sw[0] + sw[1] + sw[2] + sw[3];
        atomicAdd(&g_loss, s);
        __threadfence();
        unsigned tk = atomicAdd(&g_tickB, 1u);
        if (tk == (unsigned)(2 * HH - 1)) {
            double tot = atomicAdd(&g_loss, 0.0);
            out[0] = (float)(tot / (double)HWN);
            g_loss = 0.0;
            g_tickB = 0u;
        }
    }
}

// ---------------------------------------------------------------------------
extern "C" void kernel_launch(void* const* d_in, const int* in_sizes, int n_in,
                              void* d_out, int out_size) {
    (void)in_sizes; (void)n_in; (void)out_size;
    const float4* I = (const float4*)d_in[0];
    const float4* u = (const float4*)d_in[1];
    const float4* b = (const float4*)d_in[2];
    const float4* e = (const float4*)d_in[3];

    static bool attr_done = false;
    if (!attr_done) {
        cudaFuncSetAttribute(k1_vert, cudaFuncAttributeMaxDynamicSharedMemorySize,
                             K1_SMEM);
        cudaFuncSetAttribute(k4b_vert, cudaFuncAttributeMaxDynamicSharedMemorySize,
                             K4B_SMEM);
        attr_done = true;
    }

    dim3 g1(W4 / K1_T, HH / SEG1);   // (8, 64) for k1
    dim3 g4(W4 / K4B_T, HH / SEGB);  // (8, 64) for k4b
    dim3 gh(2, HH);                  // half-row blocks for k2/k5

    k1_vert<<<g1, K1_T, K1_SMEM>>>(I, b);
    k2_hor<<<gh, 128>>>(I, e, u);
    k4a_elem<<<HWN4 / 256, 256>>>(I, e, u);
    k4b_vert<<<g4, K4B_T, K4B_SMEM>>>();
    k5_hor<<<gh, 128>>>(I, b, (float*)d_out);
}